// round 14
// baseline (speedup 1.0000x reference)
#include <cuda_runtime.h>
#include <cuda_fp16.h>
#include <cstdint>

#define TOK      1024
#define HIDDEN   4096
#define NQH      32
#define NKVH     8
#define HD       128
#define QKV_N    6144
#define TOTAL_KV 3072
#define CACHE_LEN 8192

// ---------------- scratch (static device globals; allocation-free) ----------------
__device__ __half g_xh[TOK * HIDDEN];
__device__ __half g_w1h[HIDDEN * QKV_N];
__device__ __half g_w2h[HIDDEN * HIDDEN];
__device__ __half g_xqkvh[TOK * QKV_N];   // k/v heads (q goes straight to g_qh)
__device__ __half g_qh[TOK * HIDDEN];
__device__ __half g_keysh[TOTAL_KV * NKVH * HD];
__device__ __half g_valsh[TOTAL_KV * NKVH * HD];
__device__ __half g_attnh[TOK * HIDDEN];

// ---------------- helpers ----------------
__device__ __forceinline__ uint32_t smem_u32(const void* p) {
    uint32_t a;
    asm("{ .reg .u64 t; cvta.to.shared.u64 t, %1; cvt.u32.u64 %0, t; }" : "=r"(a) : "l"(p));
    return a;
}

__device__ __forceinline__ void mma_f16(float* d, const uint32_t* a, const uint32_t* b) {
    asm volatile(
        "mma.sync.aligned.m16n8k16.row.col.f32.f16.f16.f32 "
        "{%0,%1,%2,%3}, {%4,%5,%6,%7}, {%8,%9}, {%0,%1,%2,%3};\n"
        : "+f"(d[0]), "+f"(d[1]), "+f"(d[2]), "+f"(d[3])
        : "r"(a[0]), "r"(a[1]), "r"(a[2]), "r"(a[3]), "r"(b[0]), "r"(b[1]));
}

#define LDSM_X4(r0, r1, r2, r3, addr) \
    asm volatile("ldmatrix.sync.aligned.m8n8.x4.shared.b16 {%0,%1,%2,%3}, [%4];" \
                 : "=r"(r0), "=r"(r1), "=r"(r2), "=r"(r3) : "r"(addr))
#define LDSM_X4T(r0, r1, r2, r3, addr) \
    asm volatile("ldmatrix.sync.aligned.m8n8.x4.trans.shared.b16 {%0,%1,%2,%3}, [%4];" \
                 : "=r"(r0), "=r"(r1), "=r"(r2), "=r"(r3) : "r"(addr))
#define LDSM_X2T(r0, r1, addr) \
    asm volatile("ldmatrix.sync.aligned.m8n8.x2.trans.shared.b16 {%0,%1}, [%2];" \
                 : "=r"(r0), "=r"(r1) : "r"(addr))

#define CP16(dst, src) \
    asm volatile("cp.async.cg.shared.global [%0], [%1], 16;\n" :: "r"(dst), "l"(src))
#define CP_COMMIT() asm volatile("cp.async.commit_group;\n" ::: "memory")
#define CP_WAIT1()  asm volatile("cp.async.wait_group 1;\n" ::: "memory")

// ---------------- fp32 -> fp16 conversion ----------------
__global__ void conv_f2h(const float4* __restrict__ in, __half2* __restrict__ out, int n4) {
    int i = blockIdx.x * blockDim.x + threadIdx.x;
    if (i < n4) {
        float4 v = in[i];
        out[2 * i]     = __floats2half2_rn(v.x, v.y);
        out[2 * i + 1] = __floats2half2_rn(v.z, v.w);
    }
}

// ---------------- fp16 GEMM (R6 config): BM=128, BN=128, BK=32 ----------------
// 128 threads = 4 warps (2m x 2n), warp tile 64x64. 3-stage cp.async, 2 CTAs/SM.
// MODE 0: fp32 C output. MODE 1: fused RoPE epilogue, half outputs (q->g_qh, k/v->g_xqkvh).
#define GBM 128
#define GBN 128
#define GBK 32
#define A_STR 40
#define B_STR 136
#define A_ST_B (GBM * A_STR * 2)
#define B_ST_B (GBK * B_STR * 2)
#define STAGE_B (A_ST_B + B_ST_B)
#define GSMEM (3 * STAGE_B)

// -log2(10000)/64
#define NEG_L2_1E4_OVER_64 (-0.20762050593046014f)

template <int MODE>
__global__ __launch_bounds__(128, 2) void gemm_f16(const __half* __restrict__ A,
                                                   const __half* __restrict__ B,
                                                   float* __restrict__ C,
                                                   int M, int N, int K,
                                                   const int* __restrict__ seqstarts,
                                                   const int* __restrict__ start_pos) {
    extern __shared__ char smg[];
    const uint32_t s0 = smem_u32(smg);

    const int tid = threadIdx.x, warp = tid >> 5, lane = tid & 31;
    const int wm = warp >> 1, wn = warp & 1;
    const int g = lane >> 2, t4 = lane & 3;
    const int bm = blockIdx.y * GBM, bn = blockIdx.x * GBN;

    int a_row[4], a_c[4], b_row[4], b_c[4];
#pragma unroll
    for (int it = 0; it < 4; it++) {
        int idx = tid + it * 128;
        a_row[it] = idx >> 2; a_c[it] = (idx & 3) * 8;
        b_row[it] = idx >> 4; b_c[it] = (idx & 15) * 8;
    }
    uint32_t a_soff[4], b_soff[4];
#pragma unroll
    for (int it = 0; it < 4; it++) {
        a_soff[it] = (a_row[it] * A_STR + a_c[it]) * 2;
        b_soff[it] = A_ST_B + (b_row[it] * B_STR + b_c[it]) * 2;
    }

    const int NT = K / GBK;

    const int aRow = (lane & 7) + ((lane >> 3) & 1) * 8;
    const int aCol = ((lane >> 4) & 1) * 8;
    const int bR = lane & 15;
    const int bC = ((lane >> 4) & 1) * 8;

    float acc[4][8][4];
#pragma unroll
    for (int i = 0; i < 4; i++)
#pragma unroll
        for (int j = 0; j < 8; j++)
#pragma unroll
            for (int e = 0; e < 4; e++) acc[i][j][e] = 0.f;

#pragma unroll
    for (int s = 0; s < 2; s++) {
        const uint32_t base = s0 + s * STAGE_B;
        const int k0 = s * GBK;
#pragma unroll
        for (int it = 0; it < 4; it++) {
            CP16(base + a_soff[it], A + (size_t)(bm + a_row[it]) * K + k0 + a_c[it]);
            CP16(base + b_soff[it], B + (size_t)(k0 + b_row[it]) * N + bn + b_c[it]);
        }
        CP_COMMIT();
    }

    int sc = 0, sp = 2;
    for (int t = 0; t < NT; t++) {
        CP_WAIT1();
        __syncthreads();

        if (t + 2 < NT) {
            const uint32_t base = s0 + sp * STAGE_B;
            const int k0 = (t + 2) * GBK;
#pragma unroll
            for (int it = 0; it < 4; it++) {
                CP16(base + a_soff[it], A + (size_t)(bm + a_row[it]) * K + k0 + a_c[it]);
                CP16(base + b_soff[it], B + (size_t)(k0 + b_row[it]) * N + bn + b_c[it]);
            }
        }
        CP_COMMIT();

        const uint32_t sA = s0 + sc * STAGE_B;
        const uint32_t sB = sA + A_ST_B;
#pragma unroll
        for (int kk = 0; kk < GBK; kk += 16) {
            uint32_t af[4][4], bf[8][2];
#pragma unroll
            for (int mt = 0; mt < 4; mt++) {
                uint32_t addr = sA + ((wm * 64 + mt * 16 + aRow) * A_STR + kk + aCol) * 2;
                LDSM_X4(af[mt][0], af[mt][1], af[mt][2], af[mt][3], addr);
            }
#pragma unroll
            for (int pr = 0; pr < 4; pr++) {
                uint32_t addr = sB + ((kk + bR) * B_STR + wn * 64 + pr * 16 + bC) * 2;
                LDSM_X4T(bf[2 * pr][0], bf[2 * pr][1], bf[2 * pr + 1][0], bf[2 * pr + 1][1], addr);
            }
#pragma unroll
            for (int mt = 0; mt < 4; mt++)
#pragma unroll
                for (int nt = 0; nt < 8; nt++) mma_f16(acc[mt][nt], af[mt], bf[nt]);
        }
        sc = (sc + 1) % 3;
        sp = (sp + 1) % 3;
    }

    if (MODE == 0) {
#pragma unroll
        for (int mt = 0; mt < 4; mt++) {
            int r0 = bm + wm * 64 + mt * 16 + g;
#pragma unroll
            for (int nt = 0; nt < 8; nt++) {
                int c0 = bn + wn * 64 + nt * 8 + 2 * t4;
                *(float2*)&C[(size_t)r0 * N + c0]       = make_float2(acc[mt][nt][0], acc[mt][nt][1]);
                *(float2*)&C[(size_t)(r0 + 8) * N + c0] = make_float2(acc[mt][nt][2], acc[mt][nt][3]);
            }
        }
    } else {
        // fused RoPE epilogue: cols (c0, c0+1) = rotation pair (2i, 2i+1) of head c0>>7
        const int ss1 = seqstarts[1], ss2 = seqstarts[2], ss3 = seqstarts[3];
        const int sp0 = start_pos[0], sp1 = start_pos[1], sp2 = start_pos[2], sp3 = start_pos[3];
        __half2* qh2 = (__half2*)g_qh;
        __half2* kv2 = (__half2*)g_xqkvh;
#pragma unroll
        for (int mt = 0; mt < 4; mt++) {
            int r0 = bm + wm * 64 + mt * 16 + g;
            int r1 = r0 + 8;
            int b0 = (r0 >= ss1) + (r0 >= ss2) + (r0 >= ss3);
            int b1 = (r1 >= ss1) + (r1 >= ss2) + (r1 >= ss3);
            int off0 = (b0 == 0) ? sp0 : (b0 == 1) ? (sp1 - ss1) : (b0 == 2) ? (sp2 - ss2) : (sp3 - ss3);
            int off1 = (b1 == 0) ? sp0 : (b1 == 1) ? (sp1 - ss1) : (b1 == 2) ? (sp2 - ss2) : (sp3 - ss3);
            float pos0 = (float)(r0 + off0);
            float pos1 = (float)(r1 + off1);
#pragma unroll
            for (int nt = 0; nt < 8; nt++) {
                int c0 = bn + wn * 64 + nt * 8 + 2 * t4;
                int hh = c0 >> 7;
                float v0 = acc[mt][nt][0], v1 = acc[mt][nt][1];
                float v2 = acc[mt][nt][2], v3 = acc[mt][nt][3];
                if (hh < NQH + NKVH) {  // q or k head: rotate
                    int di = (c0 & 127) >> 1;
                    float invf = exp2f((float)di * NEG_L2_1E4_OVER_64);
                    float sn0, cs0, sn1, cs1;
                    sincosf(pos0 * invf, &sn0, &cs0);
                    sincosf(pos1 * invf, &sn1, &cs1);
                    float o0 = v0 * cs0 - v1 * sn0, o1 = v0 * sn0 + v1 * cs0;
                    float o2 = v2 * cs1 - v3 * sn1, o3 = v2 * sn1 + v3 * cs1;
                    v0 = o0; v1 = o1; v2 = o2; v3 = o3;
                }
                __half2 h0 = __floats2half2_rn(v0, v1);
                __half2 h1 = __floats2half2_rn(v2, v3);
                if (hh < NQH) {
                    qh2[((size_t)r0 * HIDDEN + c0) >> 1] = h0;
                    qh2[((size_t)r1 * HIDDEN + c0) >> 1] = h1;
                } else {
                    kv2[((size_t)r0 * QKV_N + c0) >> 1] = h0;
                    kv2[((size_t)r1 * QKV_N + c0) >> 1] = h1;
                }
            }
        }
    }
}

// ---------------- gather/merge KV (reads half xqkv, half output) ----------------
__global__ void gather_kv(const float* __restrict__ kv_cache,
                          const int* __restrict__ seqstarts, const int* __restrict__ kvstarts,
                          const int* __restrict__ cachestarts, const int* __restrict__ start_pos) {
    int kk = blockIdx.x;
    int h  = blockIdx.y;
    int d  = threadIdx.x;
    int b = 0;
#pragma unroll
    for (int i = 1; i < 4; i++)
        if (kk >= kvstarts[i]) b = i;
    int pkv = kk - kvstarts[b];
    __half kvv, vvv;
    if (pkv >= start_pos[b]) {
        int t = seqstarts[b] + pkv - start_pos[b];
        kvv = g_xqkvh[(size_t)t * QKV_N + (NQH + h) * HD + d];
        vvv = g_xqkvh[(size_t)t * QKV_N + (NQH + NKVH + h) * HD + d];
    } else {
        size_t cidx = (size_t)cachestarts[b] + pkv;
        kvv = __float2half_rn(kv_cache[(cidx * NKVH + h) * HD + d]);
        vvv = __float2half_rn(kv_cache[(size_t)CACHE_LEN * NKVH * HD + (cidx * NKVH + h) * HD + d]);
    }
    g_keysh[((size_t)kk * NKVH + h) * HD + d] = kvv;
    g_valsh[((size_t)kk * NKVH + h) * HD + d] = vvv;
}

// ---------------- flash attention fp16: BQ=64, KV chunks of 64 ----------------
#define KV_STR 136

__global__ __launch_bounds__(128, 3) void attn_kernel(const int* __restrict__ seqstarts,
                                                      const int* __restrict__ kvstarts,
                                                      const int* __restrict__ start_pos) {
    __shared__ __align__(16) __half Ks[64 * KV_STR];
    __shared__ __align__(16) __half Vs[64 * KV_STR];

    const int qtile = blockIdx.x, h = blockIdx.y, kvh = h >> 2;
    const int tid = threadIdx.x, warp = tid >> 5, lane = tid & 31;
    const int g = lane >> 2, t4 = lane & 3;
    const int rb = warp * 16;
    const int qbase = qtile * 64;

    int b = 0;
#pragma unroll
    for (int i = 1; i < 4; i++)
        if (qbase >= seqstarts[i]) b = i;
    const int pos0 = qbase - seqstarts[b] + start_pos[b];
    const int kv_lo = kvstarts[b];
    const int nchunk = (pos0 + 64 + 63) >> 6;

    uint32_t qf[8][4];
    {
        const uint32_t* q0 = (const uint32_t*)(g_qh + (size_t)(qbase + rb + g) * HIDDEN + h * HD);
        const uint32_t* q1 = (const uint32_t*)(g_qh + (size_t)(qbase + rb + g + 8) * HIDDEN + h * HD);
#pragma unroll
        for (int f = 0; f < 8; f++) {
            qf[f][0] = q0[f * 8 + t4];
            qf[f][1] = q1[f * 8 + t4];
            qf[f][2] = q0[f * 8 + t4 + 4];
            qf[f][3] = q1[f * 8 + t4 + 4];
        }
    }

    const uint32_t* Ks32 = (const uint32_t*)Ks;
    const uint32_t sV = smem_u32(Vs);
    const int vRow = lane & 15;

    float o[16][4];
#pragma unroll
    for (int nt = 0; nt < 16; nt++)
#pragma unroll
        for (int e = 0; e < 4; e++) o[nt][e] = 0.f;
    float m0 = -1e30f, m1 = -1e30f, l0 = 0.f, l1 = 0.f;
    const float scale = 0.08838834764831845f;

    for (int ch = 0; ch < nchunk; ch++) {
        const int kvb = ch * 64;
        __syncthreads();
#pragma unroll
        for (int it = 0; it < 8; it++) {
            int idx = tid + it * 128;
            int r = idx >> 4, c = (idx & 15) * 8;
            size_t go = (size_t)(kv_lo + kvb + r) * (NKVH * HD) + kvh * HD + c;
            *(uint4*)(&Ks[r * KV_STR + c]) = *(const uint4*)(g_keysh + go);
            *(uint4*)(&Vs[r * KV_STR + c]) = *(const uint4*)(g_valsh + go);
        }
        __syncthreads();

        float s[8][4];
#pragma unroll
        for (int nt = 0; nt < 8; nt++)
#pragma unroll
            for (int e = 0; e < 4; e++) s[nt][e] = 0.f;
#pragma unroll
        for (int f = 0; f < 8; f++) {
#pragma unroll
            for (int nt = 0; nt < 8; nt++) {
                uint32_t bb[2];
                bb[0] = Ks32[(nt * 8 + g) * (KV_STR / 2) + f * 8 + t4];
                bb[1] = Ks32[(nt * 8 + g) * (KV_STR / 2) + f * 8 + t4 + 4];
                mma_f16(s[nt], qf[f], bb);
            }
        }

        const int plim0 = pos0 + rb + g;
        const int plim1 = plim0 + 8;
        float mx0 = -1e30f, mx1 = -1e30f;
#pragma unroll
        for (int nt = 0; nt < 8; nt++) {
            int c0 = kvb + nt * 8 + 2 * t4;
            float v0 = s[nt][0] * scale; if (c0     > plim0) v0 = -1e30f;
            float v1 = s[nt][1] * scale; if (c0 + 1 > plim0) v1 = -1e30f;
            float v2 = s[nt][2] * scale; if (c0     > plim1) v2 = -1e30f;
            float v3 = s[nt][3] * scale; if (c0 + 1 > plim1) v3 = -1e30f;
            s[nt][0] = v0; s[nt][1] = v1; s[nt][2] = v2; s[nt][3] = v3;
            mx0 = fmaxf(mx0, fmaxf(v0, v1));
            mx1 = fmaxf(mx1, fmaxf(v2, v3));
        }
        mx0 = fmaxf(mx0, __shfl_xor_sync(0xffffffffu, mx0, 1));
        mx0 = fmaxf(mx0, __shfl_xor_sync(0xffffffffu, mx0, 2));
        mx1 = fmaxf(mx1, __shfl_xor_sync(0xffffffffu, mx1, 1));
        mx1 = fmaxf(mx1, __shfl_xor_sync(0xffffffffu, mx1, 2));
        float mn0 = fmaxf(m0, mx0), mn1 = fmaxf(m1, mx1);
        float al0 = __expf(m0 - mn0), al1 = __expf(m1 - mn1);
        float sum0 = 0.f, sum1 = 0.f;
#pragma unroll
        for (int nt = 0; nt < 8; nt++) {
            s[nt][0] = __expf(s[nt][0] - mn0); sum0 += s[nt][0];
            s[nt][1] = __expf(s[nt][1] - mn0); sum0 += s[nt][1];
            s[nt][2] = __expf(s[nt][2] - mn1); sum1 += s[nt][2];
            s[nt][3] = __expf(s[nt][3] - mn1); sum1 += s[nt][3];
        }
        sum0 += __shfl_xor_sync(0xffffffffu, sum0, 1);
        sum0 += __shfl_xor_sync(0xffffffffu, sum0, 2);
        sum1 += __shfl_xor_sync(0xffffffffu, sum1, 1);
        sum1 += __shfl_xor_sync(0xffffffffu, sum1, 2);
        l0 = l0 * al0 + sum0;
        l1 = l1 * al1 + sum1;
        m0 = mn0; m1 = mn1;
#pragma unroll
        for (int nt = 0; nt < 16; nt++) {
            o[nt][0] *= al0; o[nt][1] *= al0;
            o[nt][2] *= al1; o[nt][3] *= al1;
        }

        uint32_t pa[4][4];
#pragma unroll
        for (int kf = 0; kf < 4; kf++) {
            __half2 h0 = __floats2half2_rn(s[2 * kf][0], s[2 * kf][1]);
            __half2 h1 = __floats2half2_rn(s[2 * kf][2], s[2 * kf][3]);
            __half2 h2 = __floats2half2_rn(s[2 * kf + 1][0], s[2 * kf + 1][1]);
            __half2 h3 = __floats2half2_rn(s[2 * kf + 1][2], s[2 * kf + 1][3]);
            pa[kf][0] = *(uint32_t*)&h0;
            pa[kf][1] = *(uint32_t*)&h1;
            pa[kf][2] = *(uint32_t*)&h2;
            pa[kf][3] = *(uint32_t*)&h3;
        }

#pragma unroll
        for (int kf = 0; kf < 4; kf++) {
            uint32_t vbase = sV + ((kf * 16 + vRow) * KV_STR) * 2;
#pragma unroll
            for (int nt = 0; nt < 16; nt++) {
                uint32_t bb[2];
                LDSM_X2T(bb[0], bb[1], vbase + nt * 16);
                mma_f16(o[nt], pa[kf], bb);
            }
        }
    }

    float il0 = 1.f / l0, il1 = 1.f / l1;
    __half2* out2 = (__half2*)g_attnh;
#pragma unroll
    for (int nt = 0; nt < 16; nt++) {
        size_t r0 = qbase + rb + g;
        int c2 = h * (HD / 2) + nt * 4 + t4;
        out2[r0 * (HIDDEN / 2) + c2]       = __floats2half2_rn(o[nt][0] * il0, o[nt][1] * il0);
        out2[(r0 + 8) * (HIDDEN / 2) + c2] = __floats2half2_rn(o[nt][2] * il1, o[nt][3] * il1);
    }
}

// ---------------- launch ----------------
extern "C" void kernel_launch(void* const* d_in, const int* in_sizes, int n_in,
                              void* d_out, int out_size) {
    const float* x           = (const float*)d_in[0];
    const float* wqkv        = (const float*)d_in[1];
    const float* wo          = (const float*)d_in[2];
    const float* kv_cache    = (const float*)d_in[3];
    const int*   seqstarts   = (const int*)d_in[4];
    const int*   kvstarts    = (const int*)d_in[5];
    const int*   cachestarts = (const int*)d_in[6];
    const int*   start_pos   = (const int*)d_in[7];
    float*       out         = (float*)d_out;

    __half *p_xh, *p_w1h, *p_w2h, *p_attnh;
    cudaGetSymbolAddress((void**)&p_xh, g_xh);
    cudaGetSymbolAddress((void**)&p_w1h, g_w1h);
    cudaGetSymbolAddress((void**)&p_w2h, g_w2h);
    cudaGetSymbolAddress((void**)&p_attnh, g_attnh);

    static int configured = 0;
    static cudaStream_t s2;
    static cudaEvent_t evFork, evJoin;
    if (!configured) {
        cudaFuncSetAttribute(gemm_f16<0>, cudaFuncAttributeMaxDynamicSharedMemorySize, GSMEM);
        cudaFuncSetAttribute(gemm_f16<1>, cudaFuncAttributeMaxDynamicSharedMemorySize, GSMEM);
        cudaStreamCreateWithFlags(&s2, cudaStreamNonBlocking);
        cudaEventCreateWithFlags(&evFork, cudaEventDisableTiming);
        cudaEventCreateWithFlags(&evJoin, cudaEventDisableTiming);
        configured = 1;
    }

    // 0) fp32 -> fp16 conversions (x, w1 on main stream; w2 overlapped with gemm1)
    conv_f2h<<<(TOK * HIDDEN / 4 + 255) / 256, 256>>>((const float4*)x, (__half2*)p_xh, TOK * HIDDEN / 4);
    conv_f2h<<<(HIDDEN * QKV_N / 4 + 255) / 256, 256>>>((const float4*)wqkv, (__half2*)p_w1h, HIDDEN * QKV_N / 4);

    cudaEventRecord(evFork, 0);
    cudaStreamWaitEvent(s2, evFork, 0);
    conv_f2h<<<(HIDDEN * HIDDEN / 4 + 255) / 256, 256, 0, s2>>>((const float4*)wo, (__half2*)p_w2h, HIDDEN * HIDDEN / 4);
    cudaEventRecord(evJoin, s2);

    // 1) xqkv = x @ wqkv with fused RoPE (q->g_qh, k/v->g_xqkvh, all half)
    gemm_f16<1><<<dim3(QKV_N / GBN, TOK / GBM), 128, GSMEM>>>(p_xh, p_w1h, nullptr, TOK, QKV_N, HIDDEN,
                                                              seqstarts, start_pos);
    // 2) merge new k/v with cache -> half
    gather_kv<<<dim3(TOTAL_KV, NKVH), 128>>>(kv_cache, seqstarts, kvstarts, cachestarts, start_pos);
    // 3) flash attention -> g_attnh (half)
    attn_kernel<<<dim3(TOK / 64, NQH), 128>>>(seqstarts, kvstarts, start_pos);
    // 4) out = attn @ wo (fp32 out); waits for w2 conversion on s2
    cudaStreamWaitEvent(0, evJoin, 0);
    gemm_f16<0><<<dim3(HIDDEN / GBN, TOK / GBM), 128, GSMEM>>>(p_attnh, p_w2h, out, TOK, HIDDEN, HIDDEN,
                                                               nullptr, nullptr);
}

// round 17
// speedup vs baseline: 1.0905x; 1.0905x over previous
#include <cuda_runtime.h>
#include <cuda_fp16.h>
#include <cstdint>

#define TOK      1024
#define HIDDEN   4096
#define NQH      32
#define NKVH     8
#define HD       128
#define QKV_N    6144
#define TOTAL_KV 3072
#define CACHE_LEN 8192

// ---------------- scratch (static device globals; allocation-free) ----------------
__device__ __half g_xh[TOK * HIDDEN];
__device__ __half g_w1h[HIDDEN * QKV_N];
__device__ __half g_w2h[HIDDEN * HIDDEN];
__device__ float  g_xqkv[TOK * QKV_N];
__device__ __half g_qh[TOK * HIDDEN];
__device__ __half g_keysh[TOTAL_KV * NKVH * HD];
__device__ __half g_valsh[TOTAL_KV * NKVH * HD];
__device__ __half g_attnh[TOK * HIDDEN];

// ---------------- helpers ----------------
__device__ __forceinline__ uint32_t smem_u32(const void* p) {
    uint32_t a;
    asm("{ .reg .u64 t; cvta.to.shared.u64 t, %1; cvt.u32.u64 %0, t; }" : "=r"(a) : "l"(p));
    return a;
}

__device__ __forceinline__ void mma_f16(float* d, const uint32_t* a, const uint32_t* b) {
    asm volatile(
        "mma.sync.aligned.m16n8k16.row.col.f32.f16.f16.f32 "
        "{%0,%1,%2,%3}, {%4,%5,%6,%7}, {%8,%9}, {%0,%1,%2,%3};\n"
        : "+f"(d[0]), "+f"(d[1]), "+f"(d[2]), "+f"(d[3])
        : "r"(a[0]), "r"(a[1]), "r"(a[2]), "r"(a[3]), "r"(b[0]), "r"(b[1]));
}

#define LDSM_X4(r0, r1, r2, r3, addr) \
    asm volatile("ldmatrix.sync.aligned.m8n8.x4.shared.b16 {%0,%1,%2,%3}, [%4];" \
                 : "=r"(r0), "=r"(r1), "=r"(r2), "=r"(r3) : "r"(addr))
#define LDSM_X4T(r0, r1, r2, r3, addr) \
    asm volatile("ldmatrix.sync.aligned.m8n8.x4.trans.shared.b16 {%0,%1,%2,%3}, [%4];" \
                 : "=r"(r0), "=r"(r1), "=r"(r2), "=r"(r3) : "r"(addr))
#define LDSM_X2T(r0, r1, addr) \
    asm volatile("ldmatrix.sync.aligned.m8n8.x2.trans.shared.b16 {%0,%1}, [%2];" \
                 : "=r"(r0), "=r"(r1) : "r"(addr))

#define CP16(dst, src) \
    asm volatile("cp.async.cg.shared.global [%0], [%1], 16;\n" :: "r"(dst), "l"(src))
#define CP_COMMIT() asm volatile("cp.async.commit_group;\n" ::: "memory")
#define CP_WAIT1()  asm volatile("cp.async.wait_group 1;\n" ::: "memory")
#define CP_WAIT0()  asm volatile("cp.async.wait_group 0;\n" ::: "memory")

// ---------------- fp32 -> fp16 conversion ----------------
__global__ void conv_f2h(const float4* __restrict__ in, __half2* __restrict__ out, int n4) {
    int i = blockIdx.x * blockDim.x + threadIdx.x;
    if (i < n4) {
        float4 v = in[i];
        out[2 * i]     = __floats2half2_rn(v.x, v.y);
        out[2 * i + 1] = __floats2half2_rn(v.z, v.w);
    }
}

// ---------------- fp16 GEMM (R6 config): BM=128, BN=128, BK=32 ----------------
// 128 threads = 4 warps (2m x 2n), warp tile 64x64. 3-stage cp.async, 2 CTAs/SM.
#define GBM 128
#define GBN 128
#define GBK 32
#define A_STR 40
#define B_STR 136
#define A_ST_B (GBM * A_STR * 2)
#define B_ST_B (GBK * B_STR * 2)
#define STAGE_B (A_ST_B + B_ST_B)
#define GSMEM (3 * STAGE_B)

__global__ __launch_bounds__(128, 2) void gemm_f16(const __half* __restrict__ A,
                                                   const __half* __restrict__ B,
                                                   float* __restrict__ C,
                                                   int M, int N, int K) {
    extern __shared__ char smg[];
    const uint32_t s0 = smem_u32(smg);

    const int tid = threadIdx.x, warp = tid >> 5, lane = tid & 31;
    const int wm = warp >> 1, wn = warp & 1;
    const int g = lane >> 2, t4 = lane & 3;
    const int bm = blockIdx.y * GBM, bn = blockIdx.x * GBN;

    int a_row[4], a_c[4], b_row[4], b_c[4];
#pragma unroll
    for (int it = 0; it < 4; it++) {
        int idx = tid + it * 128;
        a_row[it] = idx >> 2; a_c[it] = (idx & 3) * 8;
        b_row[it] = idx >> 4; b_c[it] = (idx & 15) * 8;
    }
    uint32_t a_soff[4], b_soff[4];
#pragma unroll
    for (int it = 0; it < 4; it++) {
        a_soff[it] = (a_row[it] * A_STR + a_c[it]) * 2;
        b_soff[it] = A_ST_B + (b_row[it] * B_STR + b_c[it]) * 2;
    }

    const int NT = K / GBK;

    const int aRow = (lane & 7) + ((lane >> 3) & 1) * 8;
    const int aCol = ((lane >> 4) & 1) * 8;
    const int bR = lane & 15;
    const int bC = ((lane >> 4) & 1) * 8;

    float acc[4][8][4];
#pragma unroll
    for (int i = 0; i < 4; i++)
#pragma unroll
        for (int j = 0; j < 8; j++)
#pragma unroll
            for (int e = 0; e < 4; e++) acc[i][j][e] = 0.f;

#pragma unroll
    for (int s = 0; s < 2; s++) {
        const uint32_t base = s0 + s * STAGE_B;
        const int k0 = s * GBK;
#pragma unroll
        for (int it = 0; it < 4; it++) {
            CP16(base + a_soff[it], A + (size_t)(bm + a_row[it]) * K + k0 + a_c[it]);
            CP16(base + b_soff[it], B + (size_t)(k0 + b_row[it]) * N + bn + b_c[it]);
        }
        CP_COMMIT();
    }

    int sc = 0, sp = 2;
    for (int t = 0; t < NT; t++) {
        CP_WAIT1();
        __syncthreads();

        if (t + 2 < NT) {
            const uint32_t base = s0 + sp * STAGE_B;
            const int k0 = (t + 2) * GBK;
#pragma unroll
            for (int it = 0; it < 4; it++) {
                CP16(base + a_soff[it], A + (size_t)(bm + a_row[it]) * K + k0 + a_c[it]);
                CP16(base + b_soff[it], B + (size_t)(k0 + b_row[it]) * N + bn + b_c[it]);
            }
        }
        CP_COMMIT();

        const uint32_t sA = s0 + sc * STAGE_B;
        const uint32_t sB = sA + A_ST_B;
#pragma unroll
        for (int kk = 0; kk < GBK; kk += 16) {
            uint32_t af[4][4], bf[8][2];
#pragma unroll
            for (int mt = 0; mt < 4; mt++) {
                uint32_t addr = sA + ((wm * 64 + mt * 16 + aRow) * A_STR + kk + aCol) * 2;
                LDSM_X4(af[mt][0], af[mt][1], af[mt][2], af[mt][3], addr);
            }
#pragma unroll
            for (int pr = 0; pr < 4; pr++) {
                uint32_t addr = sB + ((kk + bR) * B_STR + wn * 64 + pr * 16 + bC) * 2;
                LDSM_X4T(bf[2 * pr][0], bf[2 * pr][1], bf[2 * pr + 1][0], bf[2 * pr + 1][1], addr);
            }
#pragma unroll
            for (int mt = 0; mt < 4; mt++)
#pragma unroll
                for (int nt = 0; nt < 8; nt++) mma_f16(acc[mt][nt], af[mt], bf[nt]);
        }
        sc = (sc + 1) % 3;
        sp = (sp + 1) % 3;
    }

#pragma unroll
    for (int mt = 0; mt < 4; mt++) {
        int r0 = bm + wm * 64 + mt * 16 + g;
#pragma unroll
        for (int nt = 0; nt < 8; nt++) {
            int c0 = bn + wn * 64 + nt * 8 + 2 * t4;
            *(float2*)&C[(size_t)r0 * N + c0]       = make_float2(acc[mt][nt][0], acc[mt][nt][1]);
            *(float2*)&C[(size_t)(r0 + 8) * N + c0] = make_float2(acc[mt][nt][2], acc[mt][nt][3]);
        }
    }
}

// ---------------- RoPE: q-heads -> g_qh (half), k-heads in-place fp32 ----------------
__global__ void rope_kernel(const int* __restrict__ seqstarts, const int* __restrict__ start_pos) {
    __shared__ float invf[64];
    int t = blockIdx.x;
    if (threadIdx.x < 64)
        invf[threadIdx.x] = powf(10000.0f, -(float)threadIdx.x / 64.0f);
    __syncthreads();
    int b = 0;
#pragma unroll
    for (int i = 1; i < 4; i++)
        if (t >= seqstarts[i]) b = i;
    float pos = (float)(t - seqstarts[b] + start_pos[b]);
    for (int w = threadIdx.x; w < (NQH + NKVH) * 64; w += blockDim.x) {
        int hh = w >> 6, i = w & 63;
        float ang = pos * invf[i];
        float s, c;
        sincosf(ang, &s, &c);
        float* p = g_xqkv + (size_t)t * QKV_N + hh * HD + 2 * i;
        float x1 = p[0], x2 = p[1];
        float r1 = x1 * c - x2 * s;
        float r2 = x1 * s + x2 * c;
        if (hh < NQH) {
            ((__half2*)g_qh)[(size_t)t * (HIDDEN / 2) + hh * 64 + i] = __floats2half2_rn(r1, r2);
        } else {
            p[0] = r1; p[1] = r2;
        }
    }
}

// ---------------- gather/merge KV (half output) ----------------
__global__ void gather_kv(const float* __restrict__ kv_cache,
                          const int* __restrict__ seqstarts, const int* __restrict__ kvstarts,
                          const int* __restrict__ cachestarts, const int* __restrict__ start_pos) {
    int kk = blockIdx.x;
    int h  = blockIdx.y;
    int d  = threadIdx.x;
    int b = 0;
#pragma unroll
    for (int i = 1; i < 4; i++)
        if (kk >= kvstarts[i]) b = i;
    int pkv = kk - kvstarts[b];
    float kvv, vvv;
    if (pkv >= start_pos[b]) {
        int t = seqstarts[b] + pkv - start_pos[b];
        kvv = g_xqkv[(size_t)t * QKV_N + (NQH + h) * HD + d];
        vvv = g_xqkv[(size_t)t * QKV_N + (NQH + NKVH + h) * HD + d];
    } else {
        size_t cidx = (size_t)cachestarts[b] + pkv;
        kvv = kv_cache[(cidx * NKVH + h) * HD + d];
        vvv = kv_cache[(size_t)CACHE_LEN * NKVH * HD + (cidx * NKVH + h) * HD + d];
    }
    g_keysh[((size_t)kk * NKVH + h) * HD + d] = __float2half_rn(kvv);
    g_valsh[((size_t)kk * NKVH + h) * HD + d] = __float2half_rn(vvv);
}

// ---------------- flash attention fp16: BQ=64, KV chunks of 64 ----------------
// 2-stage cp.async double-buffered K/V; 3 CTAs/SM (3 x 68KB dynamic smem).
#define KV_STR 136                       // halfs per row (128 + 8 pad)
#define KV_ROW_B (KV_STR * 2)            // 272 bytes
#define K_BYTES (64 * KV_ROW_B)          // 17408
#define AST_B (2 * K_BYTES)              // K + V per stage = 34816
#define ASMEM (2 * AST_B)                // 69632

__global__ __launch_bounds__(128, 3) void attn_kernel(const int* __restrict__ seqstarts,
                                                      const int* __restrict__ kvstarts,
                                                      const int* __restrict__ start_pos) {
    extern __shared__ char smb[];
    const uint32_t sKV = smem_u32(smb);

    const int qtile = blockIdx.x, h = blockIdx.y, kvh = h >> 2;
    const int tid = threadIdx.x, warp = tid >> 5, lane = tid & 31;
    const int g = lane >> 2, t4 = lane & 3;
    const int rb = warp * 16;
    const int qbase = qtile * 64;

    int b = 0;
#pragma unroll
    for (int i = 1; i < 4; i++)
        if (qbase >= seqstarts[i]) b = i;
    const int pos0 = qbase - seqstarts[b] + start_pos[b];
    const int kv_lo = kvstarts[b];
    const int nchunk = (pos0 + 64 + 63) >> 6;

    // per-thread load slots: 8 x (r, c): K and V rows
    int l_r[8], l_c[8];
#pragma unroll
    for (int it = 0; it < 8; it++) {
        int idx = tid + it * 128;
        l_r[it] = idx >> 4; l_c[it] = (idx & 15) * 8;
    }

    // Q fragments direct from gmem (half)
    uint32_t qf[8][4];
    {
        const uint32_t* q0 = (const uint32_t*)(g_qh + (size_t)(qbase + rb + g) * HIDDEN + h * HD);
        const uint32_t* q1 = (const uint32_t*)(g_qh + (size_t)(qbase + rb + g + 8) * HIDDEN + h * HD);
#pragma unroll
        for (int f = 0; f < 8; f++) {
            qf[f][0] = q0[f * 8 + t4];
            qf[f][1] = q1[f * 8 + t4];
            qf[f][2] = q0[f * 8 + t4 + 4];
            qf[f][3] = q1[f * 8 + t4 + 4];
        }
    }

    const int vRow = lane & 15;

    float o[16][4];
#pragma unroll
    for (int nt = 0; nt < 16; nt++)
#pragma unroll
        for (int e = 0; e < 4; e++) o[nt][e] = 0.f;
    float m0 = -1e30f, m1 = -1e30f, l0 = 0.f, l1 = 0.f;
    const float scale = 0.08838834764831845f;

    // prologue: issue chunk 0 loads into stage 0
#pragma unroll
    for (int it = 0; it < 8; it++) {
        size_t go = (size_t)(kv_lo + l_r[it]) * (NKVH * HD) + kvh * HD + l_c[it];
        uint32_t off = l_r[it] * KV_ROW_B + l_c[it] * 2;
        CP16(sKV + off, g_keysh + go);
        CP16(sKV + K_BYTES + off, g_valsh + go);
    }
    CP_COMMIT();

    for (int ch = 0; ch < nchunk; ch++) {
        CP_WAIT0();
        __syncthreads();

        if (ch + 1 < nchunk) {
            const uint32_t base = sKV + ((ch + 1) & 1) * AST_B;
            const int kvb1 = (ch + 1) * 64;
#pragma unroll
            for (int it = 0; it < 8; it++) {
                size_t go = (size_t)(kv_lo + kvb1 + l_r[it]) * (NKVH * HD) + kvh * HD + l_c[it];
                uint32_t off = l_r[it] * KV_ROW_B + l_c[it] * 2;
                CP16(base + off, g_keysh + go);
                CP16(base + K_BYTES + off, g_valsh + go);
            }
        }
        CP_COMMIT();

        const int kvb = ch * 64;
        const uint32_t stK = sKV + (ch & 1) * AST_B;
        const uint32_t stV = stK + K_BYTES;
        const uint32_t* Kp = (const uint32_t*)(smb + (ch & 1) * AST_B);

        // S = Q @ K^T  (16 rows x 64 kv), k frames of 16
        float s[8][4];
#pragma unroll
        for (int nt = 0; nt < 8; nt++)
#pragma unroll
            for (int e = 0; e < 4; e++) s[nt][e] = 0.f;
#pragma unroll
        for (int f = 0; f < 8; f++) {
#pragma unroll
            for (int nt = 0; nt < 8; nt++) {
                uint32_t bb[2];
                bb[0] = Kp[(nt * 8 + g) * (KV_STR / 2) + f * 8 + t4];
                bb[1] = Kp[(nt * 8 + g) * (KV_STR / 2) + f * 8 + t4 + 4];
                mma_f16(s[nt], qf[f], bb);
            }
        }

        // mask + online softmax (fp32)
        const int plim0 = pos0 + rb + g;
        const int plim1 = plim0 + 8;
        float mx0 = -1e30f, mx1 = -1e30f;
#pragma unroll
        for (int nt = 0; nt < 8; nt++) {
            int c0 = kvb + nt * 8 + 2 * t4;
            float v0 = s[nt][0] * scale; if (c0     > plim0) v0 = -1e30f;
            float v1 = s[nt][1] * scale; if (c0 + 1 > plim0) v1 = -1e30f;
            float v2 = s[nt][2] * scale; if (c0     > plim1) v2 = -1e30f;
            float v3 = s[nt][3] * scale; if (c0 + 1 > plim1) v3 = -1e30f;
            s[nt][0] = v0; s[nt][1] = v1; s[nt][2] = v2; s[nt][3] = v3;
            mx0 = fmaxf(mx0, fmaxf(v0, v1));
            mx1 = fmaxf(mx1, fmaxf(v2, v3));
        }
        mx0 = fmaxf(mx0, __shfl_xor_sync(0xffffffffu, mx0, 1));
        mx0 = fmaxf(mx0, __shfl_xor_sync(0xffffffffu, mx0, 2));
        mx1 = fmaxf(mx1, __shfl_xor_sync(0xffffffffu, mx1, 1));
        mx1 = fmaxf(mx1, __shfl_xor_sync(0xffffffffu, mx1, 2));
        float mn0 = fmaxf(m0, mx0), mn1 = fmaxf(m1, mx1);
        float al0 = __expf(m0 - mn0), al1 = __expf(m1 - mn1);
        float sum0 = 0.f, sum1 = 0.f;
#pragma unroll
        for (int nt = 0; nt < 8; nt++) {
            s[nt][0] = __expf(s[nt][0] - mn0); sum0 += s[nt][0];
            s[nt][1] = __expf(s[nt][1] - mn0); sum0 += s[nt][1];
            s[nt][2] = __expf(s[nt][2] - mn1); sum1 += s[nt][2];
            s[nt][3] = __expf(s[nt][3] - mn1); sum1 += s[nt][3];
        }
        sum0 += __shfl_xor_sync(0xffffffffu, sum0, 1);
        sum0 += __shfl_xor_sync(0xffffffffu, sum0, 2);
        sum1 += __shfl_xor_sync(0xffffffffu, sum1, 1);
        sum1 += __shfl_xor_sync(0xffffffffu, sum1, 2);
        l0 = l0 * al0 + sum0;
        l1 = l1 * al1 + sum1;
        m0 = mn0; m1 = mn1;
#pragma unroll
        for (int nt = 0; nt < 16; nt++) {
            o[nt][0] *= al0; o[nt][1] *= al0;
            o[nt][2] *= al1; o[nt][3] *= al1;
        }

        uint32_t pa[4][4];
#pragma unroll
        for (int kf = 0; kf < 4; kf++) {
            __half2 h0 = __floats2half2_rn(s[2 * kf][0], s[2 * kf][1]);
            __half2 h1 = __floats2half2_rn(s[2 * kf][2], s[2 * kf][3]);
            __half2 h2 = __floats2half2_rn(s[2 * kf + 1][0], s[2 * kf + 1][1]);
            __half2 h3 = __floats2half2_rn(s[2 * kf + 1][2], s[2 * kf + 1][3]);
            pa[kf][0] = *(uint32_t*)&h0;
            pa[kf][1] = *(uint32_t*)&h1;
            pa[kf][2] = *(uint32_t*)&h2;
            pa[kf][3] = *(uint32_t*)&h3;
        }

#pragma unroll
        for (int kf = 0; kf < 4; kf++) {
            uint32_t vbase = stV + (kf * 16 + vRow) * KV_ROW_B;
#pragma unroll
            for (int nt = 0; nt < 16; nt++) {
                uint32_t bb[2];
                LDSM_X2T(bb[0], bb[1], vbase + nt * 16);
                mma_f16(o[nt], pa[kf], bb);
            }
        }
    }

    float il0 = 1.f / l0, il1 = 1.f / l1;
    __half2* out2 = (__half2*)g_attnh;
#pragma unroll
    for (int nt = 0; nt < 16; nt++) {
        size_t r0 = qbase + rb + g;
        int c2 = h * (HD / 2) + nt * 4 + t4;
        out2[r0 * (HIDDEN / 2) + c2]       = __floats2half2_rn(o[nt][0] * il0, o[nt][1] * il0);
        out2[(r0 + 8) * (HIDDEN / 2) + c2] = __floats2half2_rn(o[nt][2] * il1, o[nt][3] * il1);
    }
}

// ---------------- launch ----------------
extern "C" void kernel_launch(void* const* d_in, const int* in_sizes, int n_in,
                              void* d_out, int out_size) {
    const float* x           = (const float*)d_in[0];
    const float* wqkv        = (const float*)d_in[1];
    const float* wo          = (const float*)d_in[2];
    const float* kv_cache    = (const float*)d_in[3];
    const int*   seqstarts   = (const int*)d_in[4];
    const int*   kvstarts    = (const int*)d_in[5];
    const int*   cachestarts = (const int*)d_in[6];
    const int*   start_pos   = (const int*)d_in[7];
    float*       out         = (float*)d_out;

    __half *p_xh, *p_w1h, *p_w2h, *p_attnh;
    float* p_xqkv;
    cudaGetSymbolAddress((void**)&p_xh, g_xh);
    cudaGetSymbolAddress((void**)&p_w1h, g_w1h);
    cudaGetSymbolAddress((void**)&p_w2h, g_w2h);
    cudaGetSymbolAddress((void**)&p_attnh, g_attnh);
    cudaGetSymbolAddress((void**)&p_xqkv, g_xqkv);

    static int configured = 0;
    static cudaStream_t s2;
    static cudaEvent_t evFork, evJoin;
    if (!configured) {
        cudaFuncSetAttribute(gemm_f16, cudaFuncAttributeMaxDynamicSharedMemorySize, GSMEM);
        cudaFuncSetAttribute(attn_kernel, cudaFuncAttributeMaxDynamicSharedMemorySize, ASMEM);
        cudaStreamCreateWithFlags(&s2, cudaStreamNonBlocking);
        cudaEventCreateWithFlags(&evFork, cudaEventDisableTiming);
        cudaEventCreateWithFlags(&evJoin, cudaEventDisableTiming);
        configured = 1;
    }

    // 0) fp32 -> fp16 conversions; w2 overlapped with gemm1 on stream 2
    conv_f2h<<<(TOK * HIDDEN / 4 + 255) / 256, 256>>>((const float4*)x, (__half2*)p_xh, TOK * HIDDEN / 4);
    conv_f2h<<<(HIDDEN * QKV_N / 4 + 255) / 256, 256>>>((const float4*)wqkv, (__half2*)p_w1h, HIDDEN * QKV_N / 4);

    cudaEventRecord(evFork, 0);
    cudaStreamWaitEvent(s2, evFork, 0);
    conv_f2h<<<(HIDDEN * HIDDEN / 4 + 255) / 256, 256, 0, s2>>>((const float4*)wo, (__half2*)p_w2h, HIDDEN * HIDDEN / 4);
    cudaEventRecord(evJoin, s2);

    // 1) xqkv = x @ wqkv (fp32 out)
    gemm_f16<<<dim3(QKV_N / GBN, TOK / GBM), 128, GSMEM>>>(p_xh, p_w1h, p_xqkv, TOK, QKV_N, HIDDEN);
    // 2) RoPE: q -> g_qh (half), k in-place fp32
    rope_kernel<<<TOK, 256>>>(seqstarts, start_pos);
    // 3) merge new k/v with cache -> half
    gather_kv<<<dim3(TOTAL_KV, NKVH), 128>>>(kv_cache, seqstarts, kvstarts, cachestarts, start_pos);
    // 4) flash attention -> g_attnh (half), cp.async KV pipeline
    attn_kernel<<<dim3(TOK / 64, NQH), 128, ASMEM>>>(seqstarts, kvstarts, start_pos);
    // 5) out = attn @ wo (fp32 out); waits for w2 conversion
    cudaStreamWaitEvent(0, evJoin, 0);
    gemm_f16<<<dim3(HIDDEN / GBN, TOK / GBM), 128, GSMEM>>>(p_attnh, p_w2h, out, TOK, HIDDEN, HIDDEN);
}